// round 12
// baseline (speedup 1.0000x reference)
#include <cuda_runtime.h>
#include <cuda_fp16.h>
#include <mma.h>
using namespace nvcuda;

#define D 96
#define HP 128                             // padded fp16 row (256B, 2 lines)
#define NMAX 50000
#define EMAX 800000
#define SCAN_B 512
#define NSCANBLK ((NMAX + SCAN_B - 1) / SCAN_B)   // 98
#define TM 64
#define LDH 104                            // half stride for staged tiles (pad 8)

// gemm smem: Whi,Wlo (96*LDH each) + Xhi,Xlo (TM*LDH each), halves
#define GEMM_SMEM_HALVES (2 * 96 * LDH + 2 * TM * LDH)
#define GEMM_SMEM_BYTES (GEMM_SMEM_HALVES * 2)

// ---------------- scratch (static device globals; no allocation) ----------
__device__ int    g_counts[NMAX];          // zero at load; re-zeroed by k_scan1
__device__ int    g_rowptr[NMAX + 1];
__device__ int    g_cursor[NMAX];
__device__ float  g_dinv[NMAX];
__device__ int4   g_adj4[EMAX / 2 + 1];    // pairs of {src, bitcast(norm)}
__device__ __half g_hh[(size_t)NMAX * HP]; // GEMM out, fp16 padded; pad stays 0
__device__ float  g_h2[(size_t)NMAX * D];  // agg out / GEMM2 in (fp32)
__device__ int    g_blockSums[NSCANBLK + 2];

// ---------------- graph preprocessing (round-7 proven structure) -----------
__global__ void k_hist(const int* __restrict__ ei, int E) {
    int e = blockIdx.x * blockDim.x + threadIdx.x;
    if (e < E) atomicAdd(&g_counts[ei[E + e]], 1);
}

// block-local exclusive scan; fuses dinv and counts re-zero.
__global__ void k_scan1(int n) {
    __shared__ int wsum[16];
    int i = blockIdx.x * SCAN_B + threadIdx.x;
    int lane = threadIdx.x & 31, wid = threadIdx.x >> 5;
    int v = 0;
    if (i < n) {
        v = g_counts[i];
        g_dinv[i] = rsqrtf((float)(v + 1));   // +1 self loop
        g_counts[i] = 0;                      // restore invariant for replay
    }
    int x = v;
#pragma unroll
    for (int o = 1; o < 32; o <<= 1) {
        int t = __shfl_up_sync(0xFFFFFFFFu, x, o);
        if (lane >= o) x += t;
    }
    if (lane == 31) wsum[wid] = x;
    __syncthreads();
    if (wid == 0) {
        int s = (lane < 16) ? wsum[lane] : 0;
#pragma unroll
        for (int o = 1; o < 16; o <<= 1) {
            int t = __shfl_up_sync(0xFFFFFFFFu, s, o);
            if (lane >= o) s += t;
        }
        if (lane < 16) wsum[lane] = s;
    }
    __syncthreads();
    int base = (wid > 0) ? wsum[wid - 1] : 0;
    if (i < n) g_rowptr[i] = base + x - v;           // exclusive (block-local)
    if (threadIdx.x == SCAN_B - 1) g_blockSums[blockIdx.x] = base + x;
}

// cross-block prefix, finalize rowptr + cursor
__global__ void k_scan3(int n, int nb) {
    __shared__ int sbase;
    int bid = blockIdx.x;
    if (threadIdx.x < 32) {
        int lane = threadIdx.x;
        int acc = 0;
        for (int b = lane; b < bid; b += 32) acc += g_blockSums[b];
#pragma unroll
        for (int o = 16; o; o >>= 1) acc += __shfl_xor_sync(0xFFFFFFFFu, acc, o);
        if (lane == 0) sbase = acc;
    }
    __syncthreads();
    int base = sbase;
    int i = bid * SCAN_B + threadIdx.x;
    if (i < n) {
        int v = g_rowptr[i] + base;
        g_rowptr[i] = v;
        g_cursor[i] = v;
    }
    if (bid == nb - 1 && threadIdx.x == 0) {
        int tot = base;
        for (int b = bid; b < nb; b++) tot += g_blockSums[b];
        g_rowptr[n] = tot;                   // total = E
    }
}

__global__ void k_scatter(const int* __restrict__ ei, int E) {
    int e = blockIdx.x * blockDim.x + threadIdx.x;
    if (e < E) {
        int s = ei[e];
        int d = ei[E + e];
        int pos = atomicAdd(&g_cursor[d], 1);
        float norm = g_dinv[s] * g_dinv[d];
        ((int2*)g_adj4)[pos] = make_int2(s, __float_as_int(norm));
    }
}

// ---------------- tensor-core GEMM: Hh[N,HP] = X[N,96] @ W[96,96] ----------
// Split-fp16 compensated HMMA: X=Xhi+Xlo, W=Whi+Wlo (fp16 residual split);
// acc += Xhi*Whi + Xhi*Wlo + Xlo*Whi (fp32 accum) -> fp32-class accuracy.
// block: 256 threads (8 warps), TM=64 rows. warp w -> m-tile w&3, n-tiles
// (w>>2)*3 + {0,1,2} of 16x16. Output staged via smem overlay -> fp16 g_hh.
__global__ __launch_bounds__(256) void k_gemm(const float* __restrict__ Xext,
                                              const float* __restrict__ W,
                                              int n, int src_sel) {
    extern __shared__ __align__(16) __half sm[];
    __half* Whi = sm;
    __half* Wlo = Whi + 96 * LDH;
    __half* Xhi = Wlo + 96 * LDH;
    __half* Xlo = Xhi + TM * LDH;
    float*  Os  = (float*)Xhi;              // overlay after compute

    const float* X = src_sel ? (const float*)g_h2 : Xext;
    int tid = threadIdx.x;

    // stage W split (fp32 -> hi fp16 + residual fp16)
    for (int i = tid; i < 96 * 96; i += 256) {
        int r = i / 96, c = i % 96;
        float v = W[i];
        __half h = __float2half_rn(v);
        Whi[r * LDH + c] = h;
        Wlo[r * LDH + c] = __float2half_rn(v - __half2float(h));
    }
    // stage X split
    int n0 = blockIdx.x * TM;
    int rows = min(TM, n - n0);
    for (int i = tid; i < TM * 96; i += 256) {
        int r = i / 96, c = i % 96;
        float v = (r < rows) ? X[(size_t)(n0 + r) * 96 + c] : 0.f;
        __half h = __float2half_rn(v);
        Xhi[r * LDH + c] = h;
        Xlo[r * LDH + c] = __float2half_rn(v - __half2float(h));
    }
    __syncthreads();

    int warp = tid >> 5;
    int mi = warp & 3;                      // m tile 0..3
    int ng = warp >> 2;                     // n group 0..1 -> tiles ng*3+{0,1,2}

    wmma::fragment<wmma::accumulator, 16, 16, 16, float> acc[3];
#pragma unroll
    for (int j = 0; j < 3; j++) wmma::fill_fragment(acc[j], 0.f);

#pragma unroll
    for (int k = 0; k < 96; k += 16) {
        wmma::fragment<wmma::matrix_a, 16, 16, 16, __half, wmma::row_major> ahi, alo;
        wmma::load_matrix_sync(ahi, &Xhi[(mi * 16) * LDH + k], LDH);
        wmma::load_matrix_sync(alo, &Xlo[(mi * 16) * LDH + k], LDH);
#pragma unroll
        for (int j = 0; j < 3; j++) {
            int nn = (ng * 3 + j) * 16;
            wmma::fragment<wmma::matrix_b, 16, 16, 16, __half, wmma::row_major> bhi, blo;
            wmma::load_matrix_sync(bhi, &Whi[k * LDH + nn], LDH);
            wmma::load_matrix_sync(blo, &Wlo[k * LDH + nn], LDH);
            wmma::mma_sync(acc[j], ahi, bhi, acc[j]);
            wmma::mma_sync(acc[j], ahi, blo, acc[j]);
            wmma::mma_sync(acc[j], alo, bhi, acc[j]);
        }
    }
    __syncthreads();                        // X tiles no longer needed

    // store accumulators to smem (fp32, ld=96), then convert to fp16 global
#pragma unroll
    for (int j = 0; j < 3; j++) {
        int nn = (ng * 3 + j) * 16;
        wmma::store_matrix_sync(&Os[(mi * 16) * 96 + nn], acc[j], 96,
                                wmma::mem_row_major);
    }
    __syncthreads();

    union H4 { __half2 h2[4]; uint4 u; };
    for (int i = tid; i < TM * 12; i += 256) {   // 12 groups of 8 floats per row
        int r = i / 12, g = i % 12;
        if (r < rows) {
            const float* src = &Os[r * 96 + g * 8];
            H4 s;
            s.h2[0] = __floats2half2_rn(src[0], src[1]);
            s.h2[1] = __floats2half2_rn(src[2], src[3]);
            s.h2[2] = __floats2half2_rn(src[4], src[5]);
            s.h2[3] = __floats2half2_rn(src[6], src[7]);
            *(uint4*)&g_hh[(size_t)(n0 + r) * HP + g * 8] = s.u;
        }
    }
}

// ---------------- aggregation: one warp per node ---------------------------
// reads g_hh (fp16, stride HP); writes g_h2 (dst_sel=0) or out (dst_sel=1).
// lane L handles features 4L..4L+3 via ONE LDG.64 (uint2 = 4 halfs) per edge;
// lanes 24-31 read the zero pad (no-op FMAs). adj int4 = 2 edges per LDG.128.
// => 1.5 LDG per edge total.
__global__ __launch_bounds__(256) void k_agg(const float* __restrict__ bias,
                                             const float* __restrict__ aptr,
                                             float* __restrict__ outExt,
                                             int n, int do_prelu, int dst_sel) {
    int warp = (blockIdx.x * blockDim.x + threadIdx.x) >> 5;
    int lane = threadIdx.x & 31;
    if (warp >= n) return;

    const __half* h = (const __half*)g_hh;
    float* out = dst_sel ? outExt : (float*)g_h2;

    float dn = g_dinv[warp];
    float dn2 = dn * dn;

    uint2 su = *(const uint2*)(h + (size_t)warp * HP + lane * 4);
    float2 sp0 = __half22float2(*(__half2*)&su.x);
    float2 sp1 = __half22float2(*(__half2*)&su.y);
    float a0 = sp0.x * dn2, a1 = sp0.y * dn2;
    float a2 = sp1.x * dn2, a3 = sp1.y * dn2;

    int e = g_rowptr[warp];
    int end = g_rowptr[warp + 1];
    const int2* adj = (const int2*)g_adj4;

    if ((e & 1) && e < end) {                 // align to int4 pairs
        int2 q = adj[e];
        float nn = __int_as_float(q.y);
        uint2 u = *(const uint2*)(h + (size_t)q.x * HP + lane * 4);
        float2 p0 = __half22float2(*(__half2*)&u.x);
        float2 p1 = __half22float2(*(__half2*)&u.y);
        a0 = fmaf(p0.x, nn, a0); a1 = fmaf(p0.y, nn, a1);
        a2 = fmaf(p1.x, nn, a2); a3 = fmaf(p1.y, nn, a3);
        e++;
    }
    for (; e + 1 < end; e += 2) {
        int4 q = *(const int4*)(adj + e);     // 2 edges, one broadcast LDG.128
        float n0 = __int_as_float(q.y);
        float n1 = __int_as_float(q.w);
        uint2 ua = *(const uint2*)(h + (size_t)q.x * HP + lane * 4);
        uint2 ub = *(const uint2*)(h + (size_t)q.z * HP + lane * 4);
        float2 pa0 = __half22float2(*(__half2*)&ua.x);
        float2 pa1 = __half22float2(*(__half2*)&ua.y);
        float2 pb0 = __half22float2(*(__half2*)&ub.x);
        float2 pb1 = __half22float2(*(__half2*)&ub.y);
        a0 = fmaf(pa0.x, n0, a0); a1 = fmaf(pa0.y, n0, a1);
        a2 = fmaf(pa1.x, n0, a2); a3 = fmaf(pa1.y, n0, a3);
        a0 = fmaf(pb0.x, n1, a0); a1 = fmaf(pb0.y, n1, a1);
        a2 = fmaf(pb1.x, n1, a2); a3 = fmaf(pb1.y, n1, a3);
    }
    if (e < end) {
        int2 q = adj[e];
        float nn = __int_as_float(q.y);
        uint2 u = *(const uint2*)(h + (size_t)q.x * HP + lane * 4);
        float2 p0 = __half22float2(*(__half2*)&u.x);
        float2 p1 = __half22float2(*(__half2*)&u.y);
        a0 = fmaf(p0.x, nn, a0); a1 = fmaf(p0.y, nn, a1);
        a2 = fmaf(p1.x, nn, a2); a3 = fmaf(p1.y, nn, a3);
    }

    if (lane < 24) {                          // features 4L..4L+3 valid
        float4 bb = ((const float4*)bias)[lane];
        a0 += bb.x; a1 += bb.y; a2 += bb.z; a3 += bb.w;
        if (do_prelu) {
            float a = aptr[0];
            a0 = (a0 > 0.f) ? a0 : a * a0;
            a1 = (a1 > 0.f) ? a1 : a * a1;
            a2 = (a2 > 0.f) ? a2 : a * a2;
            a3 = (a3 > 0.f) ? a3 : a * a3;
        }
        ((float4*)(out + (size_t)warp * 96))[lane] = make_float4(a0, a1, a2, a3);
    }
}

// ---------------- launch ---------------------------------------------------
extern "C" void kernel_launch(void* const* d_in, const int* in_sizes, int n_in,
                              void* d_out, int out_size) {
    const float* x  = (const float*)d_in[0];
    const int*   ei = (const int*)d_in[1];      // int32! (JAX x64 disabled)
    const float* W1 = (const float*)d_in[2];
    const float* b1 = (const float*)d_in[3];
    const float* a1 = (const float*)d_in[4];
    const float* W2 = (const float*)d_in[5];
    const float* b2 = (const float*)d_in[6];
    float*       out = (float*)d_out;

    int N = in_sizes[0] / D;
    int E = in_sizes[1] / 2;

    int nscan = (N + SCAN_B - 1) / SCAN_B;
    int gemm_blocks = (N + TM - 1) / TM;
    int agg_blocks = (N * 32 + 255) / 256;

    cudaFuncSetAttribute(k_gemm, cudaFuncAttributeMaxDynamicSharedMemorySize,
                         GEMM_SMEM_BYTES);

    // 1) GEMM1 (tensor cores)
    k_gemm<<<gemm_blocks, 256, GEMM_SMEM_BYTES>>>(x, W1, N, 0);
    // 2-5) graph preprocessing
    k_hist<<<(E + 255) / 256, 256>>>(ei, E);
    k_scan1<<<nscan, SCAN_B>>>(N);
    k_scan3<<<nscan, SCAN_B>>>(N, nscan);
    k_scatter<<<(E + 255) / 256, 256>>>(ei, E);
    // 6) layer-1 aggregate + PReLU -> g_h2
    k_agg<<<agg_blocks, 256>>>(b1, a1, out, N, 1, 0);
    // 7) GEMM2: g_h2 @ W2 -> g_hh
    k_gemm<<<gemm_blocks, 256, GEMM_SMEM_BYTES>>>(x /*unused*/, W2, N, 1);
    // 8) layer-2 aggregate -> out
    k_agg<<<agg_blocks, 256>>>(b2, a1, out, N, 0, 1);
}

// round 13
// speedup vs baseline: 1.0418x; 1.0418x over previous
#include <cuda_runtime.h>
#include <cuda_fp16.h>
#include <mma.h>
using namespace nvcuda;

#define D 96
#define HP 96                              // fp16 row stride (192B = 6 sectors)
#define NMAX 50000
#define EMAX 800000
#define SCAN_B 512
#define NSCANBLK ((NMAX + SCAN_B - 1) / SCAN_B)   // 98
#define TM 64
#define LDH 104                            // half stride for staged tiles (pad 8)

// gemm smem: Whi,Wlo (96*LDH each) + Xhi,Xlo (TM*LDH each), halves
#define GEMM_SMEM_HALVES (2 * 96 * LDH + 2 * TM * LDH)
#define GEMM_SMEM_BYTES (GEMM_SMEM_HALVES * 2)

// ---------------- scratch (static device globals; no allocation) ----------
__device__ int    g_counts[NMAX];          // zero at load; re-zeroed by k_scan1
__device__ int    g_rowptr[NMAX + 1];
__device__ int    g_cursor[NMAX];
__device__ float  g_dinv[NMAX];
__device__ int4   g_adj4[EMAX / 2 + 1];    // pairs of {src, bitcast(norm)}
__device__ __half g_hh[(size_t)NMAX * HP]; // GEMM out (fp16, unpadded rows)
__device__ float  g_h2[(size_t)NMAX * D];  // agg out / GEMM2 in (fp32)
__device__ int    g_blockSums[NSCANBLK + 2];

// ---------------- graph preprocessing (round-7 proven structure) -----------
__global__ void k_hist(const int* __restrict__ ei, int E) {
    int e = blockIdx.x * blockDim.x + threadIdx.x;
    if (e < E) atomicAdd(&g_counts[ei[E + e]], 1);
}

// block-local exclusive scan; fuses dinv and counts re-zero.
__global__ void k_scan1(int n) {
    __shared__ int wsum[16];
    int i = blockIdx.x * SCAN_B + threadIdx.x;
    int lane = threadIdx.x & 31, wid = threadIdx.x >> 5;
    int v = 0;
    if (i < n) {
        v = g_counts[i];
        g_dinv[i] = rsqrtf((float)(v + 1));   // +1 self loop
        g_counts[i] = 0;                      // restore invariant for replay
    }
    int x = v;
#pragma unroll
    for (int o = 1; o < 32; o <<= 1) {
        int t = __shfl_up_sync(0xFFFFFFFFu, x, o);
        if (lane >= o) x += t;
    }
    if (lane == 31) wsum[wid] = x;
    __syncthreads();
    if (wid == 0) {
        int s = (lane < 16) ? wsum[lane] : 0;
#pragma unroll
        for (int o = 1; o < 16; o <<= 1) {
            int t = __shfl_up_sync(0xFFFFFFFFu, s, o);
            if (lane >= o) s += t;
        }
        if (lane < 16) wsum[lane] = s;
    }
    __syncthreads();
    int base = (wid > 0) ? wsum[wid - 1] : 0;
    if (i < n) g_rowptr[i] = base + x - v;           // exclusive (block-local)
    if (threadIdx.x == SCAN_B - 1) g_blockSums[blockIdx.x] = base + x;
}

// cross-block prefix, finalize rowptr + cursor
__global__ void k_scan3(int n, int nb) {
    __shared__ int sbase;
    int bid = blockIdx.x;
    if (threadIdx.x < 32) {
        int lane = threadIdx.x;
        int acc = 0;
        for (int b = lane; b < bid; b += 32) acc += g_blockSums[b];
#pragma unroll
        for (int o = 16; o; o >>= 1) acc += __shfl_xor_sync(0xFFFFFFFFu, acc, o);
        if (lane == 0) sbase = acc;
    }
    __syncthreads();
    int base = sbase;
    int i = bid * SCAN_B + threadIdx.x;
    if (i < n) {
        int v = g_rowptr[i] + base;
        g_rowptr[i] = v;
        g_cursor[i] = v;
    }
    if (bid == nb - 1 && threadIdx.x == 0) {
        int tot = base;
        for (int b = bid; b < nb; b++) tot += g_blockSums[b];
        g_rowptr[n] = tot;                   // total = E
    }
}

__global__ void k_scatter(const int* __restrict__ ei, int E) {
    int e = blockIdx.x * blockDim.x + threadIdx.x;
    if (e < E) {
        int s = ei[e];
        int d = ei[E + e];
        int pos = atomicAdd(&g_cursor[d], 1);
        float norm = g_dinv[s] * g_dinv[d];
        ((int2*)g_adj4)[pos] = make_int2(s, __float_as_int(norm));
    }
}

// ---------------- tensor-core GEMM: Hh[N,HP] = X[N,96] @ W[96,96] ----------
// Split-fp16 compensated HMMA: X=Xhi+Xlo, W=Whi+Wlo (fp16 residual split);
// acc += Xhi*Whi + Xhi*Wlo + Xlo*Whi (fp32 accum) -> fp32-class accuracy.
// block: 256 threads (8 warps), TM=64 rows. warp w -> m-tile w&3, n-tiles
// (w>>2)*3 + {0,1,2} of 16x16. Output staged via smem overlay -> fp16 g_hh.
__global__ __launch_bounds__(256) void k_gemm(const float* __restrict__ Xext,
                                              const float* __restrict__ W,
                                              int n, int src_sel) {
    extern __shared__ __align__(16) __half sm[];
    __half* Whi = sm;
    __half* Wlo = Whi + 96 * LDH;
    __half* Xhi = Wlo + 96 * LDH;
    __half* Xlo = Xhi + TM * LDH;
    float*  Os  = (float*)Xhi;              // overlay after compute

    const float* X = src_sel ? (const float*)g_h2 : Xext;
    int tid = threadIdx.x;

    // stage W split (fp32 -> hi fp16 + residual fp16)
    for (int i = tid; i < 96 * 96; i += 256) {
        int r = i / 96, c = i % 96;
        float v = W[i];
        __half h = __float2half_rn(v);
        Whi[r * LDH + c] = h;
        Wlo[r * LDH + c] = __float2half_rn(v - __half2float(h));
    }
    // stage X split
    int n0 = blockIdx.x * TM;
    int rows = min(TM, n - n0);
    for (int i = tid; i < TM * 96; i += 256) {
        int r = i / 96, c = i % 96;
        float v = (r < rows) ? X[(size_t)(n0 + r) * 96 + c] : 0.f;
        __half h = __float2half_rn(v);
        Xhi[r * LDH + c] = h;
        Xlo[r * LDH + c] = __float2half_rn(v - __half2float(h));
    }
    __syncthreads();

    int warp = tid >> 5;
    int mi = warp & 3;                      // m tile 0..3
    int ng = warp >> 2;                     // n group 0..1 -> tiles ng*3+{0,1,2}

    wmma::fragment<wmma::accumulator, 16, 16, 16, float> acc[3];
#pragma unroll
    for (int j = 0; j < 3; j++) wmma::fill_fragment(acc[j], 0.f);

#pragma unroll
    for (int k = 0; k < 96; k += 16) {
        wmma::fragment<wmma::matrix_a, 16, 16, 16, __half, wmma::row_major> ahi, alo;
        wmma::load_matrix_sync(ahi, &Xhi[(mi * 16) * LDH + k], LDH);
        wmma::load_matrix_sync(alo, &Xlo[(mi * 16) * LDH + k], LDH);
#pragma unroll
        for (int j = 0; j < 3; j++) {
            int nn = (ng * 3 + j) * 16;
            wmma::fragment<wmma::matrix_b, 16, 16, 16, __half, wmma::row_major> bhi, blo;
            wmma::load_matrix_sync(bhi, &Whi[k * LDH + nn], LDH);
            wmma::load_matrix_sync(blo, &Wlo[k * LDH + nn], LDH);
            wmma::mma_sync(acc[j], ahi, bhi, acc[j]);
            wmma::mma_sync(acc[j], ahi, blo, acc[j]);
            wmma::mma_sync(acc[j], alo, bhi, acc[j]);
        }
    }
    __syncthreads();                        // X tiles no longer needed

    // store accumulators to smem (fp32, ld=96), then convert to fp16 global
#pragma unroll
    for (int j = 0; j < 3; j++) {
        int nn = (ng * 3 + j) * 16;
        wmma::store_matrix_sync(&Os[(mi * 16) * 96 + nn], acc[j], 96,
                                wmma::mem_row_major);
    }
    __syncthreads();

    union H4 { __half2 h2[4]; uint4 u; };
    for (int i = tid; i < TM * 12; i += 256) {   // 12 groups of 8 floats per row
        int r = i / 12, g = i % 12;
        if (r < rows) {
            const float* src = &Os[r * 96 + g * 8];
            H4 s;
            s.h2[0] = __floats2half2_rn(src[0], src[1]);
            s.h2[1] = __floats2half2_rn(src[2], src[3]);
            s.h2[2] = __floats2half2_rn(src[4], src[5]);
            s.h2[3] = __floats2half2_rn(src[6], src[7]);
            *(uint4*)&g_hh[(size_t)(n0 + r) * HP + g * 8] = s.u;
        }
    }
}

// ---------------- aggregation: one warp per node ---------------------------
// reads g_hh (fp16, 192B rows = 6 sectors); writes g_h2 or out.
// lane L (<24) handles features 4L..4L+3 via one LDG.64; lanes 24-31 idle
// (loads predicated to zero -> no extra L2 sectors). adj int4 = 2 edges per
// broadcast LDG.128. 4-edge unrolled for MLP.
__global__ __launch_bounds__(256) void k_agg(const float* __restrict__ bias,
                                             const float* __restrict__ aptr,
                                             float* __restrict__ outExt,
                                             int n, int do_prelu, int dst_sel) {
    int warp = (blockIdx.x * blockDim.x + threadIdx.x) >> 5;
    int lane = threadIdx.x & 31;
    if (warp >= n) return;

    const __half* h = (const __half*)g_hh;
    float* out = dst_sel ? outExt : (float*)g_h2;
    bool active = lane < 24;
    const uint2 zz = make_uint2(0u, 0u);

    float dn = g_dinv[warp];
    float dn2 = dn * dn;

    uint2 su = active ? *(const uint2*)(h + (size_t)warp * HP + lane * 4) : zz;
    float2 sp0 = __half22float2(*(__half2*)&su.x);
    float2 sp1 = __half22float2(*(__half2*)&su.y);
    float a0 = sp0.x * dn2, a1 = sp0.y * dn2;
    float a2 = sp1.x * dn2, a3 = sp1.y * dn2;

    int e = g_rowptr[warp];
    int end = g_rowptr[warp + 1];
    const int2* adj = (const int2*)g_adj4;

    if ((e & 1) && e < end) {                 // align to int4 pairs
        int2 q = adj[e];
        float nn = __int_as_float(q.y);
        uint2 u = active ? *(const uint2*)(h + (size_t)q.x * HP + lane * 4) : zz;
        float2 p0 = __half22float2(*(__half2*)&u.x);
        float2 p1 = __half22float2(*(__half2*)&u.y);
        a0 = fmaf(p0.x, nn, a0); a1 = fmaf(p0.y, nn, a1);
        a2 = fmaf(p1.x, nn, a2); a3 = fmaf(p1.y, nn, a3);
        e++;
    }
    for (; e + 3 < end; e += 4) {             // 4 edges: 2 adj LDG.128 + 4 LDG.64
        int4 qa = *(const int4*)(adj + e);
        int4 qb = *(const int4*)(adj + e + 2);
        uint2 u0 = active ? *(const uint2*)(h + (size_t)qa.x * HP + lane * 4) : zz;
        uint2 u1 = active ? *(const uint2*)(h + (size_t)qa.z * HP + lane * 4) : zz;
        uint2 u2 = active ? *(const uint2*)(h + (size_t)qb.x * HP + lane * 4) : zz;
        uint2 u3 = active ? *(const uint2*)(h + (size_t)qb.z * HP + lane * 4) : zz;
        float n0 = __int_as_float(qa.y), n1 = __int_as_float(qa.w);
        float n2 = __int_as_float(qb.y), n3 = __int_as_float(qb.w);
        float2 p00 = __half22float2(*(__half2*)&u0.x);
        float2 p01 = __half22float2(*(__half2*)&u0.y);
        float2 p10 = __half22float2(*(__half2*)&u1.x);
        float2 p11 = __half22float2(*(__half2*)&u1.y);
        float2 p20 = __half22float2(*(__half2*)&u2.x);
        float2 p21 = __half22float2(*(__half2*)&u2.y);
        float2 p30 = __half22float2(*(__half2*)&u3.x);
        float2 p31 = __half22float2(*(__half2*)&u3.y);
        a0 = fmaf(p00.x, n0, a0); a1 = fmaf(p00.y, n0, a1);
        a2 = fmaf(p01.x, n0, a2); a3 = fmaf(p01.y, n0, a3);
        a0 = fmaf(p10.x, n1, a0); a1 = fmaf(p10.y, n1, a1);
        a2 = fmaf(p11.x, n1, a2); a3 = fmaf(p11.y, n1, a3);
        a0 = fmaf(p20.x, n2, a0); a1 = fmaf(p20.y, n2, a1);
        a2 = fmaf(p21.x, n2, a2); a3 = fmaf(p21.y, n2, a3);
        a0 = fmaf(p30.x, n3, a0); a1 = fmaf(p30.y, n3, a1);
        a2 = fmaf(p31.x, n3, a2); a3 = fmaf(p31.y, n3, a3);
    }
    for (; e + 1 < end; e += 2) {
        int4 q = *(const int4*)(adj + e);
        uint2 u0 = active ? *(const uint2*)(h + (size_t)q.x * HP + lane * 4) : zz;
        uint2 u1 = active ? *(const uint2*)(h + (size_t)q.z * HP + lane * 4) : zz;
        float n0 = __int_as_float(q.y), n1 = __int_as_float(q.w);
        float2 p00 = __half22float2(*(__half2*)&u0.x);
        float2 p01 = __half22float2(*(__half2*)&u0.y);
        float2 p10 = __half22float2(*(__half2*)&u1.x);
        float2 p11 = __half22float2(*(__half2*)&u1.y);
        a0 = fmaf(p00.x, n0, a0); a1 = fmaf(p00.y, n0, a1);
        a2 = fmaf(p01.x, n0, a2); a3 = fmaf(p01.y, n0, a3);
        a0 = fmaf(p10.x, n1, a0); a1 = fmaf(p10.y, n1, a1);
        a2 = fmaf(p11.x, n1, a2); a3 = fmaf(p11.y, n1, a3);
    }
    if (e < end) {
        int2 q = adj[e];
        float nn = __int_as_float(q.y);
        uint2 u = active ? *(const uint2*)(h + (size_t)q.x * HP + lane * 4) : zz;
        float2 p0 = __half22float2(*(__half2*)&u.x);
        float2 p1 = __half22float2(*(__half2*)&u.y);
        a0 = fmaf(p0.x, nn, a0); a1 = fmaf(p0.y, nn, a1);
        a2 = fmaf(p1.x, nn, a2); a3 = fmaf(p1.y, nn, a3);
    }

    if (active) {                             // features 4L..4L+3 valid
        float4 bb = ((const float4*)bias)[lane];
        a0 += bb.x; a1 += bb.y; a2 += bb.z; a3 += bb.w;
        if (do_prelu) {
            float a = aptr[0];
            a0 = (a0 > 0.f) ? a0 : a * a0;
            a1 = (a1 > 0.f) ? a1 : a * a1;
            a2 = (a2 > 0.f) ? a2 : a * a2;
            a3 = (a3 > 0.f) ? a3 : a * a3;
        }
        ((float4*)(out + (size_t)warp * 96))[lane] = make_float4(a0, a1, a2, a3);
    }
}

// ---------------- launch ---------------------------------------------------
extern "C" void kernel_launch(void* const* d_in, const int* in_sizes, int n_in,
                              void* d_out, int out_size) {
    const float* x  = (const float*)d_in[0];
    const int*   ei = (const int*)d_in[1];      // int32! (JAX x64 disabled)
    const float* W1 = (const float*)d_in[2];
    const float* b1 = (const float*)d_in[3];
    const float* a1 = (const float*)d_in[4];
    const float* W2 = (const float*)d_in[5];
    const float* b2 = (const float*)d_in[6];
    float*       out = (float*)d_out;

    int N = in_sizes[0] / D;
    int E = in_sizes[1] / 2;

    int nscan = (N + SCAN_B - 1) / SCAN_B;
    int gemm_blocks = (N + TM - 1) / TM;
    int agg_blocks = (N * 32 + 255) / 256;

    cudaFuncSetAttribute(k_gemm, cudaFuncAttributeMaxDynamicSharedMemorySize,
                         GEMM_SMEM_BYTES);

    // 1) GEMM1 (tensor cores)
    k_gemm<<<gemm_blocks, 256, GEMM_SMEM_BYTES>>>(x, W1, N, 0);
    // 2-5) graph preprocessing
    k_hist<<<(E + 255) / 256, 256>>>(ei, E);
    k_scan1<<<nscan, SCAN_B>>>(N);
    k_scan3<<<nscan, SCAN_B>>>(N, nscan);
    k_scatter<<<(E + 255) / 256, 256>>>(ei, E);
    // 6) layer-1 aggregate + PReLU -> g_h2
    k_agg<<<agg_blocks, 256>>>(b1, a1, out, N, 1, 0);
    // 7) GEMM2: g_h2 @ W2 -> g_hh
    k_gemm<<<gemm_blocks, 256, GEMM_SMEM_BYTES>>>(x /*unused*/, W2, N, 1);
    // 8) layer-2 aggregate -> out
    k_agg<<<agg_blocks, 256>>>(b2, a1, out, N, 0, 1);
}